// round 10
// baseline (speedup 1.0000x reference)
#include <cuda_runtime.h>
#include <cuda_bf16.h>
#include <math.h>
#include <stdint.h>

#define D_MODEL 4096
#define D_IN1   4112
#define D_CTRL  64
#define BATCH   4
#define SEQ     2048
#define BS_TOT  8192

// ---------------- GEMM tiling ----------------
#define MTILE    128
#define KSPLIT   4
#define KPER     (D_MODEL / KSPLIT)     // 1024
#define KC       32                     // k elems per chunk
#define NCHUNK   (KPER / KC)            // 32
#define NST      3
#define AROWF    40                     // A row stride (floats)
#define BROWH    40                     // B row stride (bf16)
#define A_STG_B  (MTILE * AROWF * 4)    // 20480 B
#define B_STG_B  (D_CTRL * BROWH * 2)   // 5120 B
#define B_BASE_B (NST * A_STG_B)        // 61440
#define SMEM_B   (B_BASE_B + NST * B_STG_B + 16)

// EMA constants
#define ALPHA  0.9f
#define ONEM   0.1f
#define A4F    0.6561f                   // 0.9^4
#define A128F  1.3900845237714473e-06f   // 0.9^128

__device__ __align__(16) __nv_bfloat16 g_weff[D_CTRL * D_MODEL];   // 512 KiB
__device__ __align__(16) float g_partial[BS_TOT * KSPLIT * D_CTRL]; // 8 MiB
__device__ __align__(16) float g_delta[BS_TOT];

// ---------------- helpers ----------------
__device__ __forceinline__ uint32_t smem_u32(const void* p) {
    uint32_t a;
    asm("{ .reg .u64 t; cvta.to.shared.u64 t, %1; cvt.u32.u64 %0, t; }" : "=r"(a) : "l"(p));
    return a;
}
__device__ __forceinline__ void cp16(uint32_t dst, const void* src) {
    asm volatile("cp.async.cg.shared.global [%0], [%1], 16;" :: "r"(dst), "l"(src));
}
__device__ __forceinline__ uint32_t pack_bf16(float hi, float lo) {
    uint32_t r;
    asm("cvt.rn.bf16x2.f32 %0, %1, %2;" : "=r"(r) : "f"(hi), "f"(lo));
    return r;
}
__device__ __forceinline__ void mma_bf16(float* d, const uint32_t* a, const uint32_t* b) {
    asm volatile(
        "mma.sync.aligned.m16n8k16.row.col.f32.bf16.bf16.f32 "
        "{%0,%1,%2,%3}, {%4,%5,%6,%7}, {%8,%9}, {%0,%1,%2,%3};"
        : "+f"(d[0]), "+f"(d[1]), "+f"(d[2]), "+f"(d[3])
        : "r"(a[0]), "r"(a[1]), "r"(a[2]), "r"(a[3]), "r"(b[0]), "r"(b[1]));
}
__device__ __forceinline__ float gelu_exact(float x) {
    return 0.5f * x * (1.0f + erff(x * 0.7071067811865476f));
}
__device__ __forceinline__ float softplus_f(float x) {
    return fmaxf(x, 0.0f) + log1pf(expf(-fabsf(x)));
}

// ============================================================
// Kernel 1: Weff (bf16) = W1[:, :4096] + W1[:, 4096:] @ W_fiber
// grid (4, 64), block 256  (proven)
// ============================================================
__global__ void weff_kernel(const float* __restrict__ W1,
                            const float* __restrict__ Wf) {
    __shared__ float tail[16];
    const int k = blockIdx.y;
    if (threadIdx.x < 16) tail[threadIdx.x] = W1[(size_t)k * D_IN1 + D_MODEL + threadIdx.x];
    __syncthreads();
    const int d4 = blockIdx.x * 256 + threadIdx.x;
    float4 v = *(const float4*)&W1[(size_t)k * D_IN1 + d4 * 4];
#pragma unroll
    for (int f = 0; f < 16; ++f) {
        float4 wf = *(const float4*)&Wf[(size_t)f * D_MODEL + d4 * 4];
        float t = tail[f];
        v.x = fmaf(t, wf.x, v.x);
        v.y = fmaf(t, wf.y, v.y);
        v.z = fmaf(t, wf.z, v.z);
        v.w = fmaf(t, wf.w, v.w);
    }
    uint2 pk;
    pk.x = pack_bf16(v.y, v.x);
    pk.y = pack_bf16(v.w, v.z);
    *(uint2*)&g_weff[(size_t)k * D_MODEL + d4 * 4] = pk;
}

// ============================================================
// Kernel 2: split-K bf16 mma GEMM -> g_partial  (champion, unchanged)
// grid (64, 4), 256 threads (8 warps), warp = 16 rows x 64 cols
// ============================================================
__global__ void __launch_bounds__(256, 2)
gemm_mma_kernel(const float* __restrict__ hidden) {
    extern __shared__ char smc[];
    const uint32_t sb = smem_u32(smc);
    const float* smA = (const float*)smc;

    const int tid  = threadIdx.x;
    const int w    = tid >> 5;
    const int lane = tid & 31;
    const int g    = lane >> 2;
    const int tig  = lane & 3;
    const int rowbase = blockIdx.x * MTILE;
    const int ks      = blockIdx.y;
    const int kbase   = ks * KPER;

    float acc[8][4];
#pragma unroll
    for (int n = 0; n < 8; ++n)
#pragma unroll
        for (int j = 0; j < 4; ++j) acc[n][j] = 0.0f;

    const int arow = tid >> 1;
    const int ahalf = tid & 1;
    const float* gA = hidden + (size_t)(rowbase + arow) * D_MODEL + kbase + ahalf * 16;
    const uint32_t aDst0 = sb + (uint32_t)(arow * AROWF + ahalf * 16) * 4;
    const int brow = tid >> 2;
    const int bunit = tid & 3;
    const __nv_bfloat16* gB = g_weff + (size_t)brow * D_MODEL + kbase + bunit * 8;
    const uint32_t bDst0 = sb + B_BASE_B + (uint32_t)(brow * BROWH + bunit * 8) * 2;

    const uint32_t lmAddr0 = sb + B_BASE_B
                           + (uint32_t)((lane & 7) * (BROWH * 2) + (lane >> 3) * 16);

#pragma unroll
    for (int s = 0; s < NST; ++s) {
        const uint32_t aD = aDst0 + s * A_STG_B;
        const float* aS = gA + s * KC;
#pragma unroll
        for (int q = 0; q < 4; ++q) cp16(aD + q * 16, aS + q * 4);
        cp16(bDst0 + s * B_STG_B, gB + s * KC);
        asm volatile("cp.async.commit_group;" ::: "memory");
    }

    for (int c = 0; c < NCHUNK; ++c) {
        const int s = c % NST;
        asm volatile("cp.async.wait_group 2;" ::: "memory");
        __syncthreads();

        uint32_t bq[8][4];
        {
            const uint32_t lmS = lmAddr0 + s * B_STG_B;
#pragma unroll
            for (int n = 0; n < 8; ++n) {
                asm volatile(
                    "ldmatrix.sync.aligned.m8n8.x4.shared.b16 {%0,%1,%2,%3}, [%4];"
                    : "=r"(bq[n][0]), "=r"(bq[n][1]), "=r"(bq[n][2]), "=r"(bq[n][3])
                    : "r"(lmS + n * (8 * BROWH * 2)));
            }
        }

        const int aBaseF = s * (A_STG_B / 4) + (w * 16 + g) * AROWF;
#pragma unroll
        for (int kk = 0; kk < 2; ++kk) {
            const int k0 = kk * 16 + 2 * tig;
            uint32_t a[4];
            {
                const int r = aBaseF + k0;
                float2 p0 = *(const float2*)&smA[r];
                float2 p1 = *(const float2*)&smA[r + 8];
                float2 p2 = *(const float2*)&smA[r + 8 * AROWF];
                float2 p3 = *(const float2*)&smA[r + 8 * AROWF + 8];
                a[0] = pack_bf16(p0.y, p0.x);
                a[1] = pack_bf16(p2.y, p2.x);
                a[2] = pack_bf16(p1.y, p1.x);
                a[3] = pack_bf16(p3.y, p3.x);
            }
#pragma unroll
            for (int n = 0; n < 8; ++n)
                mma_bf16(acc[n], a, &bq[n][2 * kk]);
        }
        __syncthreads();

        const int cn = c + NST;
        if (cn < NCHUNK) {
            const uint32_t aD = aDst0 + s * A_STG_B;
            const float* aS = gA + cn * KC;
#pragma unroll
            for (int q = 0; q < 4; ++q) cp16(aD + q * 16, aS + q * 4);
            cp16(bDst0 + s * B_STG_B, gB + cn * KC);
        }
        asm volatile("cp.async.commit_group;" ::: "memory");
    }

    const int row0 = rowbase + w * 16 + g;
#pragma unroll
    for (int n = 0; n < 8; ++n) {
        const int col = 8 * n + 2 * tig;
        *(float2*)&g_partial[((size_t)row0 * 4 + ks) * 64 + col] =
            make_float2(acc[n][0], acc[n][1]);
        *(float2*)&g_partial[((size_t)(row0 + 8) * 4 + ks) * 64 + col] =
            make_float2(acc[n][2], acc[n][3]);
    }
}

// ============================================================
// Kernel 3: reduce split-K partials + GELU dot W2 + softplus -> g_delta
// ============================================================
__global__ void __launch_bounds__(256)
reduce_kernel(const float* __restrict__ b1,
              const float* __restrict__ W2,
              const float* __restrict__ b2) {
    const int w = threadIdx.x >> 5, lane = threadIdx.x & 31;
    const int row = blockIdx.x * 8 + w;
    const int col = 2 * lane;

    float2 s = make_float2(0.0f, 0.0f);
#pragma unroll
    for (int ks = 0; ks < KSPLIT; ++ks) {
        float2 p = *(const float2*)&g_partial[((size_t)row * 4 + ks) * 64 + col];
        s.x += p.x;
        s.y += p.y;
    }
    float v = gelu_exact(s.x + b1[col]) * W2[col]
            + gelu_exact(s.y + b1[col + 1]) * W2[col + 1];
#pragma unroll
    for (int off = 16; off > 0; off >>= 1)
        v += __shfl_xor_sync(0xffffffffu, v, off);
    if (lane == 0) g_delta[row] = softplus_f(v + b2[0]);
}

// ============================================================
// Kernel 4: merged EMA scan + gate + mean
// grid 4 x 512; CTA = one batch of 2048; thread = 4 elems
// CTA 0 additionally computes the global mean.
// ============================================================
__global__ void __launch_bounds__(512)
ema_kernel(const float* __restrict__ lam_p, float* __restrict__ out) {
    __shared__ float wtot[16], warpH[16], msum[16];
    const int b = blockIdx.x;
    const int tid = threadIdx.x;
    const int warp = tid >> 5, lane = tid & 31;
    const int base = b * SEQ + tid * 4;

    float4 x = *(const float4*)(g_delta + base);
    float d[4] = {x.x, x.y, x.z, x.w};

    // serial EMA over 4 elems
    float s = 0.0f;
#pragma unroll
    for (int j = 0; j < 4; ++j) s = fmaf(ALPHA, s, ONEM * d[j]);

    // warp inclusive affine scan (ratio A4 per 4-elem lane segment)
    float t = s, Ak = A4F;
#pragma unroll
    for (int off = 1; off < 32; off <<= 1) {
        float v = __shfl_up_sync(0xffffffffu, t, off);
        if (lane >= off) t = fmaf(Ak, v, t);
        Ak *= Ak;
    }
    if (lane == 31) wtot[warp] = t;
    __syncthreads();

    // cross-warp compose (16 steps, ratio A128 per 128-elem warp span)
    if (tid == 0) {
        float c = 0.0f;
#pragma unroll
        for (int j = 0; j < 16; ++j) {
            warpH[j] = c;
            c = fmaf(A128F, c, wtot[j]);
        }
    }
    __syncthreads();

    const float Hw = warpH[warp];
    const float texcl = __shfl_up_sync(0xffffffffu, t, 1);
    float h = fmaf(Hw, __powf(A4F, (float)lane), (lane > 0) ? texcl : 0.0f);

    const float lam = lam_p[0];
    float fb[4], gb[4];
#pragma unroll
    for (int j = 0; j < 4; ++j) {
        h = fmaf(ALPHA, h, ONEM * d[j]);
        fb[j] = h;
        gb[j] = __fdividef(1.0f, 1.0f + __expf(lam * h));
    }
    *(float4*)(out + base)          = make_float4(gb[0], gb[1], gb[2], gb[3]);
    *(float4*)(out + BS_TOT + base) = make_float4(fb[0], fb[1], fb[2], fb[3]);

    // global mean: CTA 0 re-reads all deltas (512 thr x 16 elems)
    if (b == 0) {
        float su = 0.0f;
        const float4* dv = (const float4*)(g_delta + tid * 16);
#pragma unroll
        for (int q = 0; q < 4; ++q) {
            float4 y = dv[q];
            su += y.x + y.y + y.z + y.w;
        }
#pragma unroll
        for (int off = 16; off > 0; off >>= 1)
            su += __shfl_xor_sync(0xffffffffu, su, off);
        if (lane == 0) msum[warp] = su;
        __syncthreads();
        if (tid == 0) {
            float tot = 0.0f;
#pragma unroll
            for (int j = 0; j < 16; ++j) tot += msum[j];
            out[2 * BS_TOT] = tot * (1.0f / (float)BS_TOT);
        }
    }
}

// ============================================================
extern "C" void kernel_launch(void* const* d_in, const int* in_sizes, int n_in,
                              void* d_out, int out_size) {
    const float* hidden = (const float*)d_in[0];
    const float* Wf     = (const float*)d_in[1];
    const float* W1     = (const float*)d_in[2];
    const float* b1     = (const float*)d_in[3];
    const float* W2     = (const float*)d_in[4];
    const float* b2     = (const float*)d_in[5];
    const float* lam    = (const float*)d_in[6];
    float* out = (float*)d_out;

    static int inited = 0;
    if (!inited) {
        cudaFuncSetAttribute(gemm_mma_kernel,
                             cudaFuncAttributeMaxDynamicSharedMemorySize, SMEM_B);
        inited = 1;
    }

    weff_kernel<<<dim3(4, D_CTRL), 256>>>(W1, Wf);
    gemm_mma_kernel<<<dim3(BS_TOT / MTILE, KSPLIT), 256, SMEM_B>>>(hidden);
    reduce_kernel<<<BS_TOT / 8, 256>>>(b1, W2, b2);
    ema_kernel<<<4, 512>>>(lam, out);
}

// round 11
// speedup vs baseline: 1.5916x; 1.5916x over previous
#include <cuda_runtime.h>
#include <cuda_bf16.h>
#include <math.h>
#include <stdint.h>

#define D_MODEL 4096
#define D_IN1   4112
#define D_CTRL  64
#define BATCH   4
#define SEQ     2048
#define BS_TOT  8192

// ---------------- GEMM tiling ----------------
#define MTILE    128
#define KSPLIT   4
#define KPER     (D_MODEL / KSPLIT)     // 1024
#define KC       32                     // k elems per chunk
#define NCHUNK   (KPER / KC)            // 32
#define NST      3
#define AROWF    40                     // A row stride (floats)
#define BROWH    40                     // B row stride (bf16)
#define A_STG_B  (MTILE * AROWF * 4)    // 20480 B
#define B_STG_B  (D_CTRL * BROWH * 2)   // 5120 B
#define B_BASE_B (NST * A_STG_B)        // 61440
#define SMEM_B   (B_BASE_B + NST * B_STG_B + 16)

__device__ __align__(16) __nv_bfloat16 g_weff[D_CTRL * D_MODEL];   // 512 KiB
__device__ __align__(16) float g_partial[BS_TOT * KSPLIT * D_CTRL]; // 8 MiB
__device__ __align__(16) float g_delta[BS_TOT];
__device__ __align__(16) float g_carry[64];

// ---------------- helpers ----------------
__device__ __forceinline__ uint32_t smem_u32(const void* p) {
    uint32_t a;
    asm("{ .reg .u64 t; cvta.to.shared.u64 t, %1; cvt.u32.u64 %0, t; }" : "=r"(a) : "l"(p));
    return a;
}
__device__ __forceinline__ void cp16(uint32_t dst, const void* src) {
    asm volatile("cp.async.cg.shared.global [%0], [%1], 16;" :: "r"(dst), "l"(src));
}
__device__ __forceinline__ uint32_t pack_bf16(float hi, float lo) {
    uint32_t r;
    asm("cvt.rn.bf16x2.f32 %0, %1, %2;" : "=r"(r) : "f"(hi), "f"(lo));
    return r;
}
__device__ __forceinline__ void mma_bf16(float* d, const uint32_t* a, const uint32_t* b) {
    asm volatile(
        "mma.sync.aligned.m16n8k16.row.col.f32.bf16.bf16.f32 "
        "{%0,%1,%2,%3}, {%4,%5,%6,%7}, {%8,%9}, {%0,%1,%2,%3};"
        : "+f"(d[0]), "+f"(d[1]), "+f"(d[2]), "+f"(d[3])
        : "r"(a[0]), "r"(a[1]), "r"(a[2]), "r"(a[3]), "r"(b[0]), "r"(b[1]));
}
__device__ __forceinline__ float gelu_exact(float x) {
    return 0.5f * x * (1.0f + erff(x * 0.7071067811865476f));
}
__device__ __forceinline__ float softplus_f(float x) {
    return fmaxf(x, 0.0f) + log1pf(expf(-fabsf(x)));
}

// ============================================================
// Kernel 1: Weff (bf16) = W1[:, :4096] + W1[:, 4096:] @ W_fiber
// grid (4, 64), block 256  (proven)
// ============================================================
__global__ void weff_kernel(const float* __restrict__ W1,
                            const float* __restrict__ Wf) {
    __shared__ float tail[16];
    const int k = blockIdx.y;
    if (threadIdx.x < 16) tail[threadIdx.x] = W1[(size_t)k * D_IN1 + D_MODEL + threadIdx.x];
    __syncthreads();
    const int d4 = blockIdx.x * 256 + threadIdx.x;
    float4 v = *(const float4*)&W1[(size_t)k * D_IN1 + d4 * 4];
#pragma unroll
    for (int f = 0; f < 16; ++f) {
        float4 wf = *(const float4*)&Wf[(size_t)f * D_MODEL + d4 * 4];
        float t = tail[f];
        v.x = fmaf(t, wf.x, v.x);
        v.y = fmaf(t, wf.y, v.y);
        v.z = fmaf(t, wf.z, v.z);
        v.w = fmaf(t, wf.w, v.w);
    }
    uint2 pk;
    pk.x = pack_bf16(v.y, v.x);
    pk.y = pack_bf16(v.w, v.z);
    *(uint2*)&g_weff[(size_t)k * D_MODEL + d4 * 4] = pk;
}

// ============================================================
// Kernel 2: split-K bf16 mma GEMM -> g_partial
// grid (64, 4), 512 threads (16 warps), warp = 16 rows x 32 cols
// 2 CTAs/SM -> 8 warps/SMSP
// ============================================================
__global__ void __launch_bounds__(512, 2)
gemm_mma_kernel(const float* __restrict__ hidden) {
    extern __shared__ char smc[];
    const uint32_t sb = smem_u32(smc);
    const float* smA = (const float*)smc;

    const int tid  = threadIdx.x;
    const int w    = tid >> 5;
    const int lane = tid & 31;
    const int g    = lane >> 2;
    const int tig  = lane & 3;
    const int rowgrp = w >> 1;          // 0..7
    const int colh   = w & 1;           // 0..1 (32-col half)
    const int rowbase = blockIdx.x * MTILE;
    const int ks      = blockIdx.y;
    const int kbase   = ks * KPER;

    float acc[4][4];
#pragma unroll
    for (int n = 0; n < 4; ++n)
#pragma unroll
        for (int j = 0; j < 4; ++j) acc[n][j] = 0.0f;

    // A loading: 1024 cp16/stage over 512 threads -> 2 each
    const int arow = tid >> 2;          // 0..127
    const int aq   = (tid & 3) * 2;     // quad pair base (0,2,4,6)
    const float* gA = hidden + (size_t)(rowbase + arow) * D_MODEL + kbase + aq * 4;
    const uint32_t aDst0 = sb + (uint32_t)(arow * AROWF + aq * 4) * 4;
    // B loading: 256 cp16/stage over threads 0..255
    const int brow = tid >> 2;          // valid when tid<256: 0..63
    const int bunit = tid & 3;
    const __nv_bfloat16* gB = g_weff + (size_t)brow * D_MODEL + kbase + bunit * 8;
    const uint32_t bDst0 = sb + B_BASE_B + (uint32_t)(brow * BROWH + bunit * 8) * 2;
    const bool doB = (tid < 256);

    // ldmatrix per-lane base: n-row = colh*32 + (lane&7), k-block (lane>>3)
    const uint32_t lmAddr0 = sb + B_BASE_B
        + (uint32_t)((colh * 32 + (lane & 7)) * (BROWH * 2) + (lane >> 3) * 16);

#pragma unroll
    for (int s = 0; s < NST; ++s) {
        const uint32_t aD = aDst0 + s * A_STG_B;
        const float* aS = gA + s * KC;
        cp16(aD, aS);
        cp16(aD + 16, aS + 4);
        if (doB) cp16(bDst0 + s * B_STG_B, gB + s * KC);
        asm volatile("cp.async.commit_group;" ::: "memory");
    }

    for (int c = 0; c < NCHUNK; ++c) {
        const int s = c % NST;
        asm volatile("cp.async.wait_group 2;" ::: "memory");
        __syncthreads();

        // B fragments: 4 ldmatrix.x4 per warp (covers both kk halves)
        uint32_t bq[4][4];
        {
            const uint32_t lmS = lmAddr0 + s * B_STG_B;
#pragma unroll
            for (int n = 0; n < 4; ++n) {
                asm volatile(
                    "ldmatrix.sync.aligned.m8n8.x4.shared.b16 {%0,%1,%2,%3}, [%4];"
                    : "=r"(bq[n][0]), "=r"(bq[n][1]), "=r"(bq[n][2]), "=r"(bq[n][3])
                    : "r"(lmS + n * (8 * BROWH * 2)));
            }
        }

        const int aBaseF = s * (A_STG_B / 4) + (rowgrp * 16 + g) * AROWF;
#pragma unroll
        for (int kk = 0; kk < 2; ++kk) {
            const int k0 = kk * 16 + 2 * tig;
            uint32_t a[4];
            {
                const int r = aBaseF + k0;
                float2 p0 = *(const float2*)&smA[r];
                float2 p1 = *(const float2*)&smA[r + 8];
                float2 p2 = *(const float2*)&smA[r + 8 * AROWF];
                float2 p3 = *(const float2*)&smA[r + 8 * AROWF + 8];
                a[0] = pack_bf16(p0.y, p0.x);
                a[1] = pack_bf16(p2.y, p2.x);
                a[2] = pack_bf16(p1.y, p1.x);
                a[3] = pack_bf16(p3.y, p3.x);
            }
#pragma unroll
            for (int n = 0; n < 4; ++n)
                mma_bf16(acc[n], a, &bq[n][2 * kk]);
        }
        __syncthreads();

        const int cn = c + NST;
        if (cn < NCHUNK) {
            const uint32_t aD = aDst0 + s * A_STG_B;
            const float* aS = gA + cn * KC;
            cp16(aD, aS);
            cp16(aD + 16, aS + 4);
            if (doB) cp16(bDst0 + s * B_STG_B, gB + cn * KC);
        }
        asm volatile("cp.async.commit_group;" ::: "memory");
    }

    // write partials: [row][ks][col]
    const int row0 = rowbase + rowgrp * 16 + g;
#pragma unroll
    for (int n = 0; n < 4; ++n) {
        const int col = colh * 32 + 8 * n + 2 * tig;
        *(float2*)&g_partial[((size_t)row0 * 4 + ks) * 64 + col] =
            make_float2(acc[n][0], acc[n][1]);
        *(float2*)&g_partial[((size_t)(row0 + 8) * 4 + ks) * 64 + col] =
            make_float2(acc[n][2], acc[n][3]);
    }
}

// ============================================================
// Kernel 3: reduce split-K partials + GELU dot W2 + softplus -> g_delta
// ============================================================
__global__ void __launch_bounds__(256)
reduce_kernel(const float* __restrict__ b1,
              const float* __restrict__ W2,
              const float* __restrict__ b2) {
    const int w = threadIdx.x >> 5, lane = threadIdx.x & 31;
    const int row = blockIdx.x * 8 + w;
    const int col = 2 * lane;

    float2 s = make_float2(0.0f, 0.0f);
#pragma unroll
    for (int ks = 0; ks < KSPLIT; ++ks) {
        float2 p = *(const float2*)&g_partial[((size_t)row * 4 + ks) * 64 + col];
        s.x += p.x;
        s.y += p.y;
    }
    float v = gelu_exact(s.x + b1[col]) * W2[col]
            + gelu_exact(s.y + b1[col + 1]) * W2[col + 1];
#pragma unroll
    for (int off = 16; off > 0; off >>= 1)
        v += __shfl_xor_sync(0xffffffffu, v, off);
    if (lane == 0) g_delta[row] = softplus_f(v + b2[0]);
}

// ============================================================
// Kernel 4: EMA carries + mean via hierarchical affine scan
// 1 block, 512 threads; thread = 16-elem segment  (R9 proven)
// ============================================================
__global__ void __launch_bounds__(512)
ema_carry_kernel(float* __restrict__ out) {
    __shared__ float wtot[16], wsum[16], warpH[16];
    const int tid = threadIdx.x;
    const int warp = tid >> 5, lane = tid & 31;
    const float alpha = 0.9f, onem = 0.1f;
    const float A16  = 0.18530201888518416f;     // 0.9^16
    const float A512 = 3.7339077e-24f;           // 0.9^512

    float d[16];
    const float4* dv = (const float4*)(g_delta + tid * 16);
#pragma unroll
    for (int q = 0; q < 4; ++q) {
        float4 x = dv[q];
        d[4 * q + 0] = x.x; d[4 * q + 1] = x.y; d[4 * q + 2] = x.z; d[4 * q + 3] = x.w;
    }

    float s = 0.0f, sum = 0.0f;
#pragma unroll
    for (int j = 0; j < 16; ++j) { s = fmaf(alpha, s, onem * d[j]); sum += d[j]; }
#pragma unroll
    for (int off = 16; off > 0; off >>= 1) sum += __shfl_xor_sync(0xffffffffu, sum, off);
    if (lane == 0) wsum[warp] = sum;

    float t = s, Ak = A16;
#pragma unroll
    for (int off = 1; off < 32; off <<= 1) {
        float v = __shfl_up_sync(0xffffffffu, t, off);
        if (lane >= off) t = fmaf(Ak, v, t);
        Ak *= Ak;
    }
    if (lane == 31) wtot[warp] = t;
    __syncthreads();

    if (tid < 4) {
        float carry = 0.0f;
#pragma unroll
        for (int j = 0; j < 4; ++j) {
            warpH[tid * 4 + j] = carry;
            carry = fmaf(A512, carry, wtot[tid * 4 + j]);
        }
    }
    if (tid == 0) {
        float tot = 0.0f;
#pragma unroll
        for (int j = 0; j < 16; ++j) tot += wsum[j];
        out[2 * BS_TOT] = tot * (1.0f / (float)BS_TOT);
    }
    __syncthreads();

    const float texcl = __shfl_up_sync(0xffffffffu, t, 1);
    const float h_ex = fmaf(warpH[warp], __powf(A16, (float)lane),
                            (lane > 0) ? texcl : 0.0f);
    if ((tid & 7) == 0) g_carry[tid >> 3] = h_ex;
}

// ============================================================
// Kernel 5: EMA apply + gate. grid 16 x 128; warp = 128-elem segment
// ============================================================
__global__ void __launch_bounds__(128)
ema_apply_kernel(const float* __restrict__ lam_p, float* __restrict__ out) {
    const int warp = threadIdx.x >> 5, lane = threadIdx.x & 31;
    const int seg = blockIdx.x * 4 + warp;
    const int base = seg * 128 + lane * 4;
    const float alpha = 0.9f, onem = 0.1f;
    const float A4 = 0.6561f;

    float4 x = *(const float4*)(g_delta + base);
    float d[4] = {x.x, x.y, x.z, x.w};

    float s = 0.0f;
#pragma unroll
    for (int j = 0; j < 4; ++j) s = fmaf(alpha, s, onem * d[j]);

    float t = s, Ak = A4;
#pragma unroll
    for (int off = 1; off < 32; off <<= 1) {
        float v = __shfl_up_sync(0xffffffffu, t, off);
        if (lane >= off) t = fmaf(Ak, v, t);
        Ak *= Ak;
    }
    const float texcl = __shfl_up_sync(0xffffffffu, t, 1);
    const float H = g_carry[seg];
    float h = fmaf(H, __powf(A4, (float)lane), (lane > 0) ? texcl : 0.0f);

    const float lam = lam_p[0];
    float fb[4], gb[4];
#pragma unroll
    for (int j = 0; j < 4; ++j) {
        h = fmaf(alpha, h, onem * d[j]);
        fb[j] = h;
        gb[j] = __fdividef(1.0f, 1.0f + __expf(lam * h));
    }
    *(float4*)(out + base)          = make_float4(gb[0], gb[1], gb[2], gb[3]);
    *(float4*)(out + BS_TOT + base) = make_float4(fb[0], fb[1], fb[2], fb[3]);
}

// ============================================================
extern "C" void kernel_launch(void* const* d_in, const int* in_sizes, int n_in,
                              void* d_out, int out_size) {
    const float* hidden = (const float*)d_in[0];
    const float* Wf     = (const float*)d_in[1];
    const float* W1     = (const float*)d_in[2];
    const float* b1     = (const float*)d_in[3];
    const float* W2     = (const float*)d_in[4];
    const float* b2     = (const float*)d_in[5];
    const float* lam    = (const float*)d_in[6];
    float* out = (float*)d_out;

    static int inited = 0;
    if (!inited) {
        cudaFuncSetAttribute(gemm_mma_kernel,
                             cudaFuncAttributeMaxDynamicSharedMemorySize, SMEM_B);
        inited = 1;
    }

    weff_kernel<<<dim3(4, D_CTRL), 256>>>(W1, Wf);
    gemm_mma_kernel<<<dim3(BS_TOT / MTILE, KSPLIT), 512, SMEM_B>>>(hidden);
    reduce_kernel<<<BS_TOT / 8, 256>>>(b1, W2, b2);
    ema_carry_kernel<<<1, 512>>>(out);
    ema_apply_kernel<<<16, 128>>>(lam, out);
}